// round 14
// baseline (speedup 1.0000x reference)
#include <cuda_runtime.h>
#include <cuda_fp16.h>
#include <cstdint>

#define BATCH   512
#define T_STEPS 8
#define HID     512
#define LATD    64
#define NSTEPS  4
#define OUT_O   (BATCH * 2 * LATD)
#define OUT_H   (BATCH * HID)
#define KA1     576               // 513 padded to multiple of 64 (A1 physical K)
#define KE1     (2 * KA1)         // 1152 effective K for layer-1 (W1 = [hi|lo])
#define KAZ     1024              // z buffers physical K
#define KEZ     2048              // effective K for layers 2/3
#define KAX     512               // x physical K
#define KEX     1024              // effective K for Wih

// ---------------- scratch (device globals) ----------------
__device__ float g_h  [BATCH * HID];
__device__ float g_acc[BATCH * HID];
__device__ float g_gi [T_STEPS * BATCH * 1536];   // all timesteps, batched
__device__ float g_gh [BATCH * 1536];
__device__ __half g_A1  [BATCH * KA1];            // single fp16 activations
__device__ __half g_z1b [BATCH * KAZ];
__device__ __half g_z2b [BATCH * KAZ];
__device__ __half g_xb  [T_STEPS * BATCH * KAX];
__device__ __half g_W1b [1024 * KE1];             // [hi(576) | lo(576)]
__device__ __half g_W2b [1024 * KEZ];
__device__ __half g_W3b [512 * KEZ];
__device__ __half g_Wihb[1536 * KEX];
__device__ __half g_Whhb[1536 * KE1];
__device__ __half g_Woutb[128 * KE1];

// ---------------- helpers ----------------
__device__ __forceinline__ uint32_t smem_u32(const void* p) {
    uint32_t a;
    asm("{ .reg .u64 t; cvta.to.shared.u64 t, %1; cvt.u32.u64 %0, t; }" : "=r"(a) : "l"(p));
    return a;
}
template<int N> __device__ __forceinline__ void cp_wait() {
    asm volatile("cp.async.wait_group %0;" :: "n"(N) : "memory");
}
__device__ __forceinline__ float sigm(float x) { return 1.f / (1.f + __expf(-x)); }

// ---------------- GEMM: C(MxN) = epi(A(MxKa) @ W(NxK)^T + bias) ------------
// W rows: [hi | lo] fp16 exact split (K = 2*Ka). A rows: single fp16 (Ka wide);
// the K-loop wraps A's column offset for the second W segment.
// CTA tile 64x64, 256 threads = 8 warps arranged 2M x 2N x 2K:
// warp tile 32x32, each warp accumulates HALF of each BK=64 chunk (kq),
// halves are combined once at the end via an smem fragment exchange.
constexpr int SROW = 72;   // smem row stride (fp16): 64 + 8 pad
constexpr int BK   = 64;   // K per pipeline stage
#define SMEM_BYTES (3 * 128 * SROW * 2)          // 3 stages x (64 A + 64 B) rows
#define RED_STRIDE 17                             // f32 per thread slot (16 + pad)
#define RED_REGION (4 * 32 * RED_STRIDE)          // f32 per direction (2176)

struct GemmP {
    const __half* A; int Ka;       // physical A row stride / wrap point
    const __half* W; int K;        // effective K (multiple of 64)
    const float* bias;
    // EPI 0: f32 out
    float* Cf; int ldc;
    // EPI 1: bias+swish -> fp16
    __half* Cb; int ldcb;
    // EPI 2: RK4
    const float* ts; int step;
    float kw, amul_next, tc_next; int first, last;
    float* acc; float* h; __half* A1;
};

// EPI: 0 = bias->f32, 1 = bias+swish->fp16, 2 = RK4 epilogue
template<int EPI>
__global__ __launch_bounds__(256) void gemm_mma(GemmP p) {
    extern __shared__ __align__(16) char dsm[];
    __half* sAb = (__half*)dsm;                      // 3 stages x 64*SROW
    __half* sBb = sAb + 3 * 64 * SROW;               // 3 stages x 64*SROW
    const int tid  = threadIdx.x;
    const int lane = tid & 31, wid = tid >> 5;
    const int wm = wid & 1, wn = (wid >> 1) & 1, kq = wid >> 2;
    const int mBase = blockIdx.y * 64;
    const int nBase = blockIdx.x * 64;
    const int KT = p.K / BK;

    // ac[im][j][q]: im = 16-row group within the warp's 32 rows
    float ac[2][4][4];
#pragma unroll
    for (int i = 0; i < 2; i++)
#pragma unroll
        for (int j = 0; j < 4; j++)
#pragma unroll
            for (int q = 0; q < 4; q++) ac[i][j][q] = 0.f;

    const int lrow = tid >> 3;        // 0..31
    const int lcg  = (tid & 7) * 8;   // 0..56 step 8

    auto load_stage = [&](int s, int kt) {
        int aCol = kt * BK; if (aCol >= p.Ka) aCol -= p.Ka;   // wrap for 2nd W segment
        const __half* Ag = p.A + (size_t)mBase * p.Ka + aCol;
        const __half* Wg = p.W + (size_t)nBase * p.K + kt * BK;
        const uint32_t a0 = smem_u32(sAb + s * 64 * SROW);
        const uint32_t b0 = smem_u32(sBb + s * 64 * SROW);
#pragma unroll
        for (int i = 0; i < 2; i++) {
            const int r = lrow + i * 32;
            const uint32_t d = a0 + (uint32_t)(r * SROW + lcg) * 2;
            const void* src = (const void*)(Ag + (size_t)r * p.Ka + lcg);
            asm volatile("cp.async.cg.shared.global [%0], [%1], 16;" :: "r"(d), "l"(src) : "memory");
        }
#pragma unroll
        for (int i = 0; i < 2; i++) {
            const int r = lrow + i * 32;
            const uint32_t d = b0 + (uint32_t)(r * SROW + lcg) * 2;
            const void* src = (const void*)(Wg + (size_t)r * p.K + lcg);
            asm volatile("cp.async.cg.shared.global [%0], [%1], 16;" :: "r"(d), "l"(src) : "memory");
        }
        asm volatile("cp.async.commit_group;" ::: "memory");
    };

    auto compute = [&](int s) {
        const uint32_t aB = smem_u32(sAb + s * 64 * SROW);
        const uint32_t bB = smem_u32(sBb + s * 64 * SROW);
#pragma unroll
        for (int kki = 0; kki < 32; kki += 16) {
            const int kk = kq * 32 + kki;
            uint32_t af[2][4], bf[4][2];
#pragma unroll
            for (int im = 0; im < 2; im++) {
                const uint32_t ad = aB +
                    (uint32_t)(((wm * 32 + im * 16 + (lane & 15)) * SROW + kk + (lane >> 4) * 8) * 2);
                asm volatile("ldmatrix.sync.aligned.m8n8.x4.shared.b16 {%0,%1,%2,%3}, [%4];"
                    : "=r"(af[im][0]), "=r"(af[im][1]), "=r"(af[im][2]), "=r"(af[im][3]) : "r"(ad));
            }
#pragma unroll
            for (int jp = 0; jp < 2; jp++) {
                const int n = wn * 32 + jp * 16 + (lane >> 4) * 8 + (lane & 7);
                const int c = kk + ((lane >> 3) & 1) * 8;
                const uint32_t bd = bB + (uint32_t)((n * SROW + c) * 2);
                uint32_t r0, r1, r2, r3;
                asm volatile("ldmatrix.sync.aligned.m8n8.x4.shared.b16 {%0,%1,%2,%3}, [%4];"
                    : "=r"(r0), "=r"(r1), "=r"(r2), "=r"(r3) : "r"(bd));
                bf[jp * 2][0] = r0; bf[jp * 2][1] = r1;
                bf[jp * 2 + 1][0] = r2; bf[jp * 2 + 1][1] = r3;
            }
#pragma unroll
            for (int im = 0; im < 2; im++)
#pragma unroll
                for (int j = 0; j < 4; j++)
                    asm volatile(
                        "mma.sync.aligned.m16n8k16.row.col.f32.f16.f16.f32 "
                        "{%0,%1,%2,%3}, {%4,%5,%6,%7}, {%8,%9}, {%0,%1,%2,%3};"
                        : "+f"(ac[im][j][0]), "+f"(ac[im][j][1]), "+f"(ac[im][j][2]), "+f"(ac[im][j][3])
                        : "r"(af[im][0]), "r"(af[im][1]), "r"(af[im][2]), "r"(af[im][3]),
                          "r"(bf[j][0]), "r"(bf[j][1]));
        }
    };

    load_stage(0, 0);
    if (KT > 1) load_stage(1, 1);
    for (int kt = 0; kt < KT; kt++) {
        if (kt == KT - 1) cp_wait<0>(); else cp_wait<1>();
        __syncthreads();
        if (kt + 2 < KT) load_stage((kt + 2) % 3, kt + 2);
        compute(kt % 3);
    }

    // ---- cross-kq reduction: exchange the fragment halves through smem ----
    __syncthreads();   // stage smem now dead; safe to overwrite
    float* red = (float*)dsm;
    const int slot = ((wm * 2 + wn) * 32 + lane) * RED_STRIDE;
    if (kq == 0) {     // store acc[im=1] for partner (region 0)
#pragma unroll
        for (int j = 0; j < 4; j++)
#pragma unroll
            for (int q = 0; q < 4; q++) red[slot + j * 4 + q] = ac[1][j][q];
    } else {           // store acc[im=0] for partner (region 1)
#pragma unroll
        for (int j = 0; j < 4; j++)
#pragma unroll
            for (int q = 0; q < 4; q++) red[RED_REGION + slot + j * 4 + q] = ac[0][j][q];
    }
    __syncthreads();
    if (kq == 0) {     // finalize im=0: own half + partner's half
#pragma unroll
        for (int j = 0; j < 4; j++)
#pragma unroll
            for (int q = 0; q < 4; q++) ac[0][j][q] += red[RED_REGION + slot + j * 4 + q];
    } else {           // finalize im=1
#pragma unroll
        for (int j = 0; j < 4; j++)
#pragma unroll
            for (int q = 0; q < 4; q++) ac[1][j][q] += red[slot + j * 4 + q];
    }

    // ---- epilogue: warp (wm,wn,kq) owns rows wm*32 + kq*16 + 0..15 of quadrant ----
    float (*accF)[4] = ac[kq];
    const int rb = mBase + wm * 32 + kq * 16 + (lane >> 2);
    const int cb = nBase + wn * 32 + (lane & 3) * 2;
#pragma unroll
    for (int rh = 0; rh < 2; rh++) {
        const int r = rb + rh * 8;
        float tpr = 0.f, dt = 0.f;
        if (EPI == 2) {
            tpr = p.ts[r * T_STEPS + p.step - 1];
            const float tcu = p.ts[r * T_STEPS + p.step];
            dt = (tcu - tpr) * 0.25f;
        }
#pragma unroll
        for (int j = 0; j < 4; j++) {
            const int c = cb + j * 8;
            float v0 = accF[j][rh * 2 + 0] + p.bias[c];
            float v1 = accF[j][rh * 2 + 1] + p.bias[c + 1];
            if (EPI == 0) {
                float2 st = {v0, v1};
                *(float2*)(p.Cf + (size_t)r * p.ldc + c) = st;
            } else if (EPI == 1) {
                v0 = v0 * sigm(v0);
                v1 = v1 * sigm(v1);
                *(__half2*)(p.Cb + (size_t)r * p.ldcb + c) = __floats2half2_rn(v0, v1);
            } else {  // EPI == 2: RK4
                const size_t idx = (size_t)r * HID + c;
                float a0, a1v;
                if (!p.last) {
                    const float av0 = p.first ? v0 : p.acc[idx]     + p.kw * v0;
                    const float av1 = p.first ? v1 : p.acc[idx + 1] + p.kw * v1;
                    p.acc[idx] = av0; p.acc[idx + 1] = av1;
                    a0  = p.h[idx]     + p.amul_next * dt * v0;
                    a1v = p.h[idx + 1] + p.amul_next * dt * v1;
                } else {
                    a0  = p.h[idx]     + dt * (1.f / 6.f) * (p.acc[idx]     + v0);
                    a1v = p.h[idx + 1] + dt * (1.f / 6.f) * (p.acc[idx + 1] + v1);
                    p.h[idx] = a0; p.h[idx + 1] = a1v;
                }
                *(__half2*)(p.A1 + (size_t)r * KA1 + c) = __floats2half2_rn(a0, a1v);
            }
        }
        if (EPI == 2 && nBase == 0 && wn == 0 && (lane & 3) == 0) {
            const float tn = tpr + p.tc_next * dt;
            p.A1[(size_t)r * KA1 + HID] = __float2half_rn(tn);
        }
    }
}

// ---------------- elementwise / setup kernels ----------------
__global__ void zero_f(float* p, int n) {
    int i = blockIdx.x * blockDim.x + threadIdx.x;
    if (i < n) p[i] = 0.f;
}
__global__ void zero_h(__half* p, int n) {
    int i = blockIdx.x * blockDim.x + threadIdx.x;
    if (i < n) p[i] = __float2half_rn(0.f);
}
// W[N][K] -> Wb[N][2*Kp] = [hi | lo] fp16 exact split, zero-padded cols K..Kp-1
__global__ void conv_w(const float* __restrict__ W, __half* __restrict__ Wb,
                       int N, int K, int Kp) {
    int idx = blockIdx.x * blockDim.x + threadIdx.x;
    if (idx >= N * Kp) return;
    const int n = idx / Kp, c = idx - n * Kp;
    const float v = (c < K) ? W[(size_t)n * K + c] : 0.f;
    const __half hi = __float2half_rn(v);
    Wb[(size_t)n * 2 * Kp + c]      = hi;
    Wb[(size_t)n * 2 * Kp + Kp + c] = __float2half_rn(v - __half2float(hi));
}
// x[r][s][c] -> xb[s][r][c] single fp16
__global__ void conv_x(const float* __restrict__ x, __half* __restrict__ xb) {
    int idx = blockIdx.x * blockDim.x + threadIdx.x;   // idx = r*4096 + s*512 + c
    if (idx >= BATCH * T_STEPS * KAX) return;
    const int c = idx & 511, s = (idx >> 9) & 7, r = idx >> 12;
    xb[((size_t)s * BATCH + r) * KAX + c] = __float2half_rn(x[idx]);
}
__global__ void gru_gate(const float* __restrict__ gi, const float* __restrict__ gh,
                         float* __restrict__ h, __half* __restrict__ A1,
                         const float* __restrict__ ts, int step) {
    int idx = blockIdx.x * blockDim.x + threadIdx.x;
    if (idx >= BATCH * HID) return;
    const int r = idx >> 9, j = idx & 511;
    const float* gir = gi + (size_t)r * 1536;
    const float* ghr = gh + (size_t)r * 1536;
    const float rr = sigm(gir[j] + ghr[j]);
    const float zz = sigm(gir[512 + j] + ghr[512 + j]);
    const float nn = tanhf(gir[1024 + j] + rr * ghr[1024 + j]);
    const float hn = (1.f - zz) * nn + zz * h[idx];
    h[idx] = hn;
    A1[(size_t)r * KA1 + j] = __float2half_rn(hn);
    if (j == 0) {  // time column for next step: t_prev = ts[:, step]
        A1[(size_t)r * KA1 + HID] = __float2half_rn(ts[r * T_STEPS + step]);
    }
}
__global__ void finalize_k(const float* __restrict__ h, float* __restrict__ out) {
    int i = blockIdx.x * blockDim.x + threadIdx.x;
    if (i < BATCH * HID) {
        out[OUT_O + i]         = h[i];
        out[OUT_O + OUT_H + i] = 0.f;   // c never updated -> zeros
    }
}

// ---------------- host ----------------
extern "C" void kernel_launch(void* const* d_in, const int* in_sizes, int n_in,
                              void* d_out, int out_size) {
    const float* x    = (const float*)d_in[0];
    const float* ts   = (const float*)d_in[1];
    const float* Wih  = (const float*)d_in[2];
    const float* Whh  = (const float*)d_in[3];
    const float* bih  = (const float*)d_in[4];
    const float* bhh  = (const float*)d_in[5];
    const float* Wout = (const float*)d_in[6];
    const float* bout = (const float*)d_in[7];
    const float* W1   = (const float*)d_in[8];
    const float* b1   = (const float*)d_in[9];
    const float* W2   = (const float*)d_in[10];
    const float* b2   = (const float*)d_in[11];
    const float* W3   = (const float*)d_in[12];
    const float* b3   = (const float*)d_in[13];
    float* out = (float*)d_out;

    float *h, *acc, *gi, *gh;
    __half *A1, *z1b, *z2b, *xb, *W1b, *W2b, *W3b, *Wihb, *Whhb, *Woutb;
    cudaGetSymbolAddress((void**)&h, g_h);       cudaGetSymbolAddress((void**)&acc, g_acc);
    cudaGetSymbolAddress((void**)&gi, g_gi);     cudaGetSymbolAddress((void**)&gh, g_gh);
    cudaGetSymbolAddress((void**)&A1, g_A1);     cudaGetSymbolAddress((void**)&z1b, g_z1b);
    cudaGetSymbolAddress((void**)&z2b, g_z2b);   cudaGetSymbolAddress((void**)&xb, g_xb);
    cudaGetSymbolAddress((void**)&W1b, g_W1b);   cudaGetSymbolAddress((void**)&W2b, g_W2b);
    cudaGetSymbolAddress((void**)&W3b, g_W3b);   cudaGetSymbolAddress((void**)&Wihb, g_Wihb);
    cudaGetSymbolAddress((void**)&Whhb, g_Whhb); cudaGetSymbolAddress((void**)&Woutb, g_Woutb);

    cudaFuncSetAttribute((const void*)gemm_mma<0>,
                         cudaFuncAttributeMaxDynamicSharedMemorySize, SMEM_BYTES);
    cudaFuncSetAttribute((const void*)gemm_mma<1>,
                         cudaFuncAttributeMaxDynamicSharedMemorySize, SMEM_BYTES);
    cudaFuncSetAttribute((const void*)gemm_mma<2>,
                         cudaFuncAttributeMaxDynamicSharedMemorySize, SMEM_BYTES);

    // setup: convert weights/inputs, zero state
    zero_f<<<(BATCH * HID + 255) / 256, 256>>>(h, BATCH * HID);
    zero_h<<<(BATCH * KA1 + 255) / 256, 256>>>(A1, BATCH * KA1);
    conv_w<<<(1024 * KA1 + 255) / 256, 256>>>(W1, W1b, 1024, 513, KA1);
    conv_w<<<(1024 * KAZ + 255) / 256, 256>>>(W2, W2b, 1024, 1024, KAZ);
    conv_w<<<(512 * KAZ + 255) / 256, 256>>>(W3, W3b, 512, 1024, KAZ);
    conv_w<<<(1536 * KAX + 255) / 256, 256>>>(Wih, Wihb, 1536, 512, KAX);
    conv_w<<<(1536 * KA1 + 255) / 256, 256>>>(Whh, Whhb, 1536, 512, KA1);
    conv_w<<<(128 * KA1 + 255) / 256, 256>>>(Wout, Woutb, 128, 512, KA1);
    conv_x<<<(BATCH * T_STEPS * KAX + 255) / 256, 256>>>(x, xb);

    // ALL timesteps' input-side GRU GEMM, batched: gi[s*512+r] = x_s @ Wih^T + bih
    {
        GemmP pg1 = {};
        pg1.A = xb; pg1.Ka = KAX; pg1.W = Wihb; pg1.K = KEX; pg1.bias = bih;
        pg1.Cf = gi; pg1.ldc = 1536;
        gemm_mma<0><<<dim3(24, 64), 256, SMEM_BYTES>>>(pg1);   // M=4096, N=1536
    }

    const float amuls[4] = {0.f, 0.5f, 0.5f, 1.f};
    const float tcs  [4] = {0.f, 0.5f, 0.5f, 1.f};

    for (int step = 0; step < T_STEPS; step++) {
        if (step > 0) {  // step 0: dt==0 -> ODE is exactly identity, skip
            for (int rk = 0; rk < NSTEPS; rk++) {
                for (int ev = 0; ev < 4; ev++) {
                    // z1 = swish(A1 @ W1^T + b1); K_eff = 1152
                    GemmP p1 = {};
                    p1.A = A1; p1.Ka = KA1; p1.W = W1b; p1.K = KE1; p1.bias = b1;
                    p1.Cb = z1b; p1.ldcb = KAZ;
                    gemm_mma<1><<<dim3(16, 8), 256, SMEM_BYTES>>>(p1);

                    // z2 = swish(z1 @ W2^T + b2); K_eff = 2048
                    GemmP p2 = {};
                    p2.A = z1b; p2.Ka = KAZ; p2.W = W2b; p2.K = KEZ; p2.bias = b2;
                    p2.Cb = z2b; p2.ldcb = KAZ;
                    gemm_mma<1><<<dim3(16, 8), 256, SMEM_BYTES>>>(p2);

                    // k = z2 @ W3^T + b3; fused RK4 + next-A1 build; K_eff = 2048
                    GemmP p3 = {};
                    p3.A = z2b; p3.Ka = KAZ; p3.W = W3b; p3.K = KEZ; p3.bias = b3;
                    p3.ts = ts; p3.step = step;
                    p3.first = (ev == 0); p3.last = (ev == 3);
                    p3.kw = (ev == 1 || ev == 2) ? 2.f : 1.f;
                    p3.amul_next = (ev < 3) ? amuls[ev + 1] : 0.f;
                    p3.tc_next   = (ev < 3) ? ((float)rk + tcs[ev + 1]) : (float)(rk + 1);
                    p3.acc = acc; p3.h = h; p3.A1 = A1;
                    gemm_mma<2><<<dim3(8, 8), 256, SMEM_BYTES>>>(p3);
                }
            }
        }
        // gh = h @ Whh^T + bhh; K_eff = 1152
        GemmP pg2 = {};
        pg2.A = A1; pg2.Ka = KA1; pg2.W = Whhb; pg2.K = KE1; pg2.bias = bhh;
        pg2.Cf = gh; pg2.ldc = 1536;
        gemm_mma<0><<<dim3(24, 8), 256, SMEM_BYTES>>>(pg2);

        gru_gate<<<(BATCH * HID + 255) / 256, 256>>>(
            gi + (size_t)step * BATCH * 1536, gh, h, A1, ts, step);
    }

    // out = h @ Wout^T + bout (only last timestep's output); K_eff = 1152
    GemmP po = {};
    po.A = A1; po.Ka = KA1; po.W = Woutb; po.K = KE1; po.bias = bout;
    po.Cf = out; po.ldc = 128;
    gemm_mma<0><<<dim3(2, 8), 256, SMEM_BYTES>>>(po);

    finalize_k<<<(BATCH * HID + 255) / 256, 256>>>(h, out);
}

// round 15
// speedup vs baseline: 1.0786x; 1.0786x over previous
#include <cuda_runtime.h>
#include <cuda_fp16.h>
#include <cstdint>

#define BATCH   512
#define T_STEPS 8
#define HID     512
#define LATD    64
#define NSTEPS  4
#define OUT_O   (BATCH * 2 * LATD)
#define OUT_H   (BATCH * HID)
#define KA1     576               // 513 padded to multiple of 64 (A1 physical K)
#define KE1     (2 * KA1)         // 1152 effective K for layer-1 (W1 = [hi|lo])
#define KAZ     1024              // z buffers physical K
#define KEZ     2048              // effective K for layers 2/3
#define KAX     512               // x physical K
#define KEX     1024              // effective K for Wih
#define GRID_P  128               // persistent grid size (<=148 SMs, all resident)

// ---------------- scratch (device globals) ----------------
__device__ float g_h  [BATCH * HID];
__device__ float g_acc[BATCH * HID];
__device__ float g_gi [T_STEPS * BATCH * 1536];
__device__ float g_gh [BATCH * 1536];
__device__ __half g_A1  [BATCH * KA1];
__device__ __half g_z1b [BATCH * KAZ];
__device__ __half g_z2b [BATCH * KAZ];
__device__ __half g_xb  [T_STEPS * BATCH * KAX];
__device__ __half g_W1b [1024 * KE1];
__device__ __half g_W2b [1024 * KEZ];
__device__ __half g_W3b [512 * KEZ];
__device__ __half g_Wihb[1536 * KEX];
__device__ __half g_Whhb[1536 * KE1];
__device__ __half g_Woutb[128 * KE1];
__device__ unsigned g_barrier;

// ---------------- helpers ----------------
__device__ __forceinline__ uint32_t smem_u32(const void* p) {
    uint32_t a;
    asm("{ .reg .u64 t; cvta.to.shared.u64 t, %1; cvt.u32.u64 %0, t; }" : "=r"(a) : "l"(p));
    return a;
}
template<int N> __device__ __forceinline__ void cp_wait() {
    asm volatile("cp.async.wait_group %0;" :: "n"(N) : "memory");
}
__device__ __forceinline__ float sigm(float x) { return 1.f / (1.f + __expf(-x)); }
__device__ __forceinline__ void st16cg(__half* p, __half v) {
    unsigned short u = *(unsigned short*)&v;
    asm volatile("st.global.cg.u16 [%0], %1;" :: "l"(p), "h"(u) : "memory");
}

// grid-wide barrier (all CTAs resident; cooperative-groups pattern)
__device__ __forceinline__ void gbar(unsigned& exp) {
    __syncthreads();
    __threadfence();
    exp += gridDim.x;
    if (threadIdx.x == 0) {
        atomicAdd(&g_barrier, 1u);
        unsigned v;
        do {
            asm volatile("ld.global.acquire.gpu.u32 %0, [%1];"
                         : "=r"(v) : "l"(&g_barrier) : "memory");
        } while (v < exp);
    }
    __syncthreads();
}

// ---------------- GEMM tile: C(64xBN_) at (mBase,nBase) -------------------
// W rows: [hi | lo] fp16 exact split (K = 2*Ka). A rows: single fp16 (Ka wide);
// K-loop wraps A's column offset for the second W segment.
constexpr int SROW = 72;   // smem row stride (fp16): 64 + 8 pad
constexpr int BK   = 64;
#define SMEM_BYTES (3 * 128 * SROW * 2)

struct GemmP {
    const __half* A; int Ka;
    const __half* W; int K;
    const float* bias;
    float* Cf; int ldc;                 // EPI 0
    __half* Cb; int ldcb;               // EPI 1
    const float* ts; int step;          // EPI 2
    float kw, amul_next, tc_next; int first, last;
    float* acc; float* h; __half* A1;
};

// EPI: 0 = bias->f32, 1 = bias+swish->fp16, 2 = RK4 epilogue
// 8 warps: wm=wid&3 (4 x 16 rows), wn=wid>>2 (2 x BN_/2 cols)
template<int EPI, int BN_>
__device__ __forceinline__ void gemm_tile(const GemmP& p, int mBase, int nBase, char* dsm) {
    constexpr int NJ = BN_ / 16;
    __half* sAb = (__half*)dsm;
    __half* sBb = sAb + 3 * 64 * SROW;
    const int tid  = threadIdx.x;
    const int lane = tid & 31, wid = tid >> 5;
    const int wm = wid & 3, wn = wid >> 2;
    const int KT = p.K / BK;

    float ac[NJ][4];
#pragma unroll
    for (int j = 0; j < NJ; j++)
#pragma unroll
        for (int q = 0; q < 4; q++) ac[j][q] = 0.f;

    const int lrow = tid >> 3;
    const int lcg  = (tid & 7) * 8;

    auto load_stage = [&](int s, int kt) {
        int aCol = kt * BK; if (aCol >= p.Ka) aCol -= p.Ka;
        const __half* Ag = p.A + (size_t)mBase * p.Ka + aCol;
        const __half* Wg = p.W + (size_t)nBase * p.K + kt * BK;
        const uint32_t a0 = smem_u32(sAb + s * 64 * SROW);
        const uint32_t b0 = smem_u32(sBb + s * 64 * SROW);
#pragma unroll
        for (int i = 0; i < 2; i++) {
            const int r = lrow + i * 32;
            const uint32_t d = a0 + (uint32_t)(r * SROW + lcg) * 2;
            const void* src = (const void*)(Ag + (size_t)r * p.Ka + lcg);
            asm volatile("cp.async.cg.shared.global [%0], [%1], 16;" :: "r"(d), "l"(src) : "memory");
        }
#pragma unroll
        for (int i = 0; i < (BN_ > 32 ? 2 : 1); i++) {
            const int r = lrow + i * 32;
            const uint32_t d = b0 + (uint32_t)(r * SROW + lcg) * 2;
            const void* src = (const void*)(Wg + (size_t)r * p.K + lcg);
            asm volatile("cp.async.cg.shared.global [%0], [%1], 16;" :: "r"(d), "l"(src) : "memory");
        }
        asm volatile("cp.async.commit_group;" ::: "memory");
    };

    auto compute = [&](int s) {
        const uint32_t aB = smem_u32(sAb + s * 64 * SROW);
        const uint32_t bB = smem_u32(sBb + s * 64 * SROW);
#pragma unroll
        for (int kk = 0; kk < BK; kk += 16) {
            uint32_t af[4], bf[NJ][2];
            {
                const uint32_t ad = aB +
                    (uint32_t)(((wm * 16 + (lane & 15)) * SROW + kk + (lane >> 4) * 8) * 2);
                asm volatile("ldmatrix.sync.aligned.m8n8.x4.shared.b16 {%0,%1,%2,%3}, [%4];"
                    : "=r"(af[0]), "=r"(af[1]), "=r"(af[2]), "=r"(af[3]) : "r"(ad));
            }
#pragma unroll
            for (int jp = 0; jp < NJ / 2; jp++) {
                const int n = wn * (BN_ / 2) + jp * 16 + (lane >> 4) * 8 + (lane & 7);
                const int c = kk + ((lane >> 3) & 1) * 8;
                const uint32_t bd = bB + (uint32_t)((n * SROW + c) * 2);
                uint32_t r0, r1, r2, r3;
                asm volatile("ldmatrix.sync.aligned.m8n8.x4.shared.b16 {%0,%1,%2,%3}, [%4];"
                    : "=r"(r0), "=r"(r1), "=r"(r2), "=r"(r3) : "r"(bd));
                bf[jp * 2][0] = r0; bf[jp * 2][1] = r1;
                bf[jp * 2 + 1][0] = r2; bf[jp * 2 + 1][1] = r3;
            }
#pragma unroll
            for (int j = 0; j < NJ; j++)
                asm volatile(
                    "mma.sync.aligned.m16n8k16.row.col.f32.f16.f16.f32 "
                    "{%0,%1,%2,%3}, {%4,%5,%6,%7}, {%8,%9}, {%0,%1,%2,%3};"
                    : "+f"(ac[j][0]), "+f"(ac[j][1]), "+f"(ac[j][2]), "+f"(ac[j][3])
                    : "r"(af[0]), "r"(af[1]), "r"(af[2]), "r"(af[3]),
                      "r"(bf[j][0]), "r"(bf[j][1]));
        }
    };

    load_stage(0, 0);
    if (KT > 1) load_stage(1, 1);
    for (int kt = 0; kt < KT; kt++) {
        if (kt == KT - 1) cp_wait<0>(); else cp_wait<1>();
        __syncthreads();
        if (kt + 2 < KT) load_stage((kt + 2) % 3, kt + 2);
        compute(kt % 3);
    }

    // ---- epilogue ----
    const int rb = mBase + wm * 16 + (lane >> 2);
    const int cb = nBase + wn * (BN_ / 2) + (lane & 3) * 2;
#pragma unroll
    for (int rh = 0; rh < 2; rh++) {
        const int r = rb + rh * 8;
        float tpr = 0.f, dt = 0.f;
        if (EPI == 2) {
            tpr = p.ts[r * T_STEPS + p.step - 1];
            const float tcu = p.ts[r * T_STEPS + p.step];
            dt = (tcu - tpr) * 0.25f;
        }
#pragma unroll
        for (int j = 0; j < NJ; j++) {
            const int c = cb + j * 8;
            float v0 = ac[j][rh * 2 + 0] + p.bias[c];
            float v1 = ac[j][rh * 2 + 1] + p.bias[c + 1];
            if (EPI == 0) {
                float2 st = {v0, v1};
                *(float2*)(p.Cf + (size_t)r * p.ldc + c) = st;
            } else if (EPI == 1) {
                v0 = v0 * sigm(v0);
                v1 = v1 * sigm(v1);
                *(__half2*)(p.Cb + (size_t)r * p.ldcb + c) = __floats2half2_rn(v0, v1);
            } else {  // EPI == 2: RK4
                const size_t idx = (size_t)r * HID + c;
                float a0, a1v;
                if (!p.last) {
                    const float av0 = p.first ? v0 : __ldcg(&p.acc[idx])     + p.kw * v0;
                    const float av1 = p.first ? v1 : __ldcg(&p.acc[idx + 1]) + p.kw * v1;
                    p.acc[idx] = av0; p.acc[idx + 1] = av1;
                    a0  = __ldcg(&p.h[idx])     + p.amul_next * dt * v0;
                    a1v = __ldcg(&p.h[idx + 1]) + p.amul_next * dt * v1;
                } else {
                    a0  = __ldcg(&p.h[idx])     + dt * (1.f / 6.f) * (__ldcg(&p.acc[idx])     + v0);
                    a1v = __ldcg(&p.h[idx + 1]) + dt * (1.f / 6.f) * (__ldcg(&p.acc[idx + 1]) + v1);
                    p.h[idx] = a0; p.h[idx + 1] = a1v;
                }
                *(__half2*)(p.A1 + (size_t)r * KA1 + c) = __floats2half2_rn(a0, a1v);
            }
        }
        if (EPI == 2 && nBase == 0 && wn == 0 && (lane & 3) == 0) {
            const float tn = tpr + p.tc_next * dt;
            p.A1[(size_t)r * KA1 + HID] = __float2half_rn(tn);
        }
    }
}

// standalone GEMM (for the batched gi pre-pass)
template<int EPI>
__global__ __launch_bounds__(256) void gemm_mma(GemmP p) {
    extern __shared__ __align__(16) char dsm[];
    gemm_tile<EPI, 64>(p, blockIdx.y * 64, blockIdx.x * 64, dsm);
}

// ---------------- the persistent sequence megakernel ----------------
__global__ __launch_bounds__(256) void seq_kernel(
    const float* __restrict__ ts,
    const float* __restrict__ b1, const float* __restrict__ b2,
    const float* __restrict__ b3, const float* __restrict__ bhh,
    const float* __restrict__ bout,
    const __half* W1b, const __half* W2b, const __half* W3b,
    const __half* Whhb, const __half* Woutb,
    __half* A1, __half* z1b, __half* z2b,
    float* gi, float* gh, float* h, float* acc, float* out)
{
    extern __shared__ __align__(16) char dsm[];
    const int b = blockIdx.x;
    const int tid = threadIdx.x;
    unsigned exp = 0;

    GemmP p1 = {}; p1.A = A1;  p1.Ka = KA1; p1.W = W1b; p1.K = KE1; p1.bias = b1;
    p1.Cb = z1b; p1.ldcb = KAZ;
    GemmP p2 = {}; p2.A = z1b; p2.Ka = KAZ; p2.W = W2b; p2.K = KEZ; p2.bias = b2;
    p2.Cb = z2b; p2.ldcb = KAZ;
    GemmP pg = {}; pg.A = A1;  pg.Ka = KA1; pg.W = Whhb; pg.K = KE1; pg.bias = bhh;
    pg.Cf = gh; pg.ldc = 1536;

    const float amuls[4] = {0.f, 0.5f, 0.5f, 1.f};
    const float tcs  [4] = {0.f, 0.5f, 0.5f, 1.f};

    for (int step = 0; step < T_STEPS; step++) {
        if (step > 0) {
            for (int rk = 0; rk < NSTEPS; rk++) {
                for (int ev = 0; ev < 4; ev++) {
                    // z1 = swish(A1 @ W1^T + b1): 8x16 tiles = 128 CTAs
                    gemm_tile<1, 64>(p1, (b >> 4) * 64, (b & 15) * 64, dsm);
                    gbar(exp);
                    // z2 = swish(z1 @ W2^T + b2): 128 CTAs
                    gemm_tile<1, 64>(p2, (b >> 4) * 64, (b & 15) * 64, dsm);
                    gbar(exp);
                    // k = z2 @ W3^T + b3 (+RK4): 8x8 tiles = 64 CTAs
                    if (b < 64) {
                        GemmP p3 = {};
                        p3.A = z2b; p3.Ka = KAZ; p3.W = W3b; p3.K = KEZ; p3.bias = b3;
                        p3.ts = ts; p3.step = step;
                        p3.first = (ev == 0); p3.last = (ev == 3);
                        p3.kw = (ev == 1 || ev == 2) ? 2.f : 1.f;
                        p3.amul_next = (ev < 3) ? amuls[ev + 1] : 0.f;
                        p3.tc_next   = (ev < 3) ? ((float)rk + tcs[ev + 1]) : (float)(rk + 1);
                        p3.acc = acc; p3.h = h; p3.A1 = A1;
                        gemm_tile<2, 64>(p3, (b >> 3) * 64, (b & 7) * 64, dsm);
                    }
                    gbar(exp);
                }
            }
        }
        // gh = A1 @ Whh^T + bhh: 8x24 = 192 tiles over 128 CTAs
        for (int t = b; t < 192; t += GRID_P)
            gemm_tile<0, 64>(pg, (t / 24) * 64, (t % 24) * 64, dsm);
        gbar(exp);
        // GRU gate (elementwise): 262144 elems / 32768 threads = 8 each
        {
            const float* gis = gi + (size_t)step * BATCH * 1536;
            const int base = b * 256 + tid;
#pragma unroll
            for (int q = 0; q < 8; q++) {
                const int idx = base + q * (GRID_P * 256);
                const int r = idx >> 9, j = idx & 511;
                const float gi0 = gis[(size_t)r * 1536 + j];
                const float gi1 = gis[(size_t)r * 1536 + 512 + j];
                const float gi2 = gis[(size_t)r * 1536 + 1024 + j];
                const float gh0 = __ldcg(&gh[(size_t)r * 1536 + j]);
                const float gh1 = __ldcg(&gh[(size_t)r * 1536 + 512 + j]);
                const float gh2 = __ldcg(&gh[(size_t)r * 1536 + 1024 + j]);
                const float rr = sigm(gi0 + gh0);
                const float zz = sigm(gi1 + gh1);
                const float nn = tanhf(gi2 + rr * gh2);
                const float hn = (1.f - zz) * nn + zz * __ldcg(&h[idx]);
                h[idx] = hn;
                A1[(size_t)r * KA1 + j] = __float2half_rn(hn);
                if (j == 0)
                    A1[(size_t)r * KA1 + HID] = __float2half_rn(ts[r * T_STEPS + step]);
            }
        }
        gbar(exp);
    }
    // out = h @ Wout^T + bout: 8x2 = 16 tiles; plus finalize (disjoint ranges)
    if (b < 16) {
        GemmP po = {}; po.A = A1; po.Ka = KA1; po.W = Woutb; po.K = KE1; po.bias = bout;
        po.Cf = out; po.ldc = 128;
        gemm_tile<0, 64>(po, (b >> 1) * 64, (b & 1) * 64, dsm);
    }
    {
        const int base = b * 256 + tid;
#pragma unroll
        for (int q = 0; q < 8; q++) {
            const int i = base + q * (GRID_P * 256);
            out[OUT_O + i]         = __ldcg(&h[i]);
            out[OUT_O + OUT_H + i] = 0.f;   // c never updated -> zeros
        }
    }
}

// ---------------- elementwise / setup kernels ----------------
__global__ void zero_bar() { g_barrier = 0u; }
__global__ void zero_f(float* p, int n) {
    int i = blockIdx.x * blockDim.x + threadIdx.x;
    if (i < n) p[i] = 0.f;
}
__global__ void zero_h(__half* p, int n) {
    int i = blockIdx.x * blockDim.x + threadIdx.x;
    if (i < n) p[i] = __float2half_rn(0.f);
}
__global__ void conv_w(const float* __restrict__ W, __half* __restrict__ Wb,
                       int N, int K, int Kp) {
    int idx = blockIdx.x * blockDim.x + threadIdx.x;
    if (idx >= N * Kp) return;
    const int n = idx / Kp, c = idx - n * Kp;
    const float v = (c < K) ? W[(size_t)n * K + c] : 0.f;
    const __half hi = __float2half_rn(v);
    Wb[(size_t)n * 2 * Kp + c]      = hi;
    Wb[(size_t)n * 2 * Kp + Kp + c] = __float2half_rn(v - __half2float(hi));
}
__global__ void conv_x(const float* __restrict__ x, __half* __restrict__ xb) {
    int idx = blockIdx.x * blockDim.x + threadIdx.x;
    if (idx >= BATCH * T_STEPS * KAX) return;
    const int c = idx & 511, s = (idx >> 9) & 7, r = idx >> 12;
    xb[((size_t)s * BATCH + r) * KAX + c] = __float2half_rn(x[idx]);
}

// ---------------- host ----------------
extern "C" void kernel_launch(void* const* d_in, const int* in_sizes, int n_in,
                              void* d_out, int out_size) {
    const float* x    = (const float*)d_in[0];
    const float* ts   = (const float*)d_in[1];
    const float* Wih  = (const float*)d_in[2];
    const float* Whh  = (const float*)d_in[3];
    const float* bih  = (const float*)d_in[4];
    const float* bhh  = (const float*)d_in[5];
    const float* Wout = (const float*)d_in[6];
    const float* bout = (const float*)d_in[7];
    const float* W1   = (const float*)d_in[8];
    const float* b1   = (const float*)d_in[9];
    const float* W2   = (const float*)d_in[10];
    const float* b2   = (const float*)d_in[11];
    const float* W3   = (const float*)d_in[12];
    const float* b3   = (const float*)d_in[13];
    float* out = (float*)d_out;

    float *h, *acc, *gi, *gh;
    __half *A1, *z1b, *z2b, *xb, *W1b, *W2b, *W3b, *Wihb, *Whhb, *Woutb;
    cudaGetSymbolAddress((void**)&h, g_h);       cudaGetSymbolAddress((void**)&acc, g_acc);
    cudaGetSymbolAddress((void**)&gi, g_gi);     cudaGetSymbolAddress((void**)&gh, g_gh);
    cudaGetSymbolAddress((void**)&A1, g_A1);     cudaGetSymbolAddress((void**)&z1b, g_z1b);
    cudaGetSymbolAddress((void**)&z2b, g_z2b);   cudaGetSymbolAddress((void**)&xb, g_xb);
    cudaGetSymbolAddress((void**)&W1b, g_W1b);   cudaGetSymbolAddress((void**)&W2b, g_W2b);
    cudaGetSymbolAddress((void**)&W3b, g_W3b);   cudaGetSymbolAddress((void**)&Wihb, g_Wihb);
    cudaGetSymbolAddress((void**)&Whhb, g_Whhb); cudaGetSymbolAddress((void**)&Woutb, g_Woutb);

    cudaFuncSetAttribute((const void*)gemm_mma<0>,
                         cudaFuncAttributeMaxDynamicSharedMemorySize, SMEM_BYTES);
    cudaFuncSetAttribute((const void*)seq_kernel,
                         cudaFuncAttributeMaxDynamicSharedMemorySize, SMEM_BYTES);

    // setup: convert weights/inputs, zero state
    zero_f<<<(BATCH * HID + 255) / 256, 256>>>(h, BATCH * HID);
    zero_h<<<(BATCH * KA1 + 255) / 256, 256>>>(A1, BATCH * KA1);
    zero_bar<<<1, 1>>>();
    conv_w<<<(1024 * KA1 + 255) / 256, 256>>>(W1, W1b, 1024, 513, KA1);
    conv_w<<<(1024 * KAZ + 255) / 256, 256>>>(W2, W2b, 1024, 1024, KAZ);
    conv_w<<<(512 * KAZ + 255) / 256, 256>>>(W3, W3b, 512, 1024, KAZ);
    conv_w<<<(1536 * KAX + 255) / 256, 256>>>(Wih, Wihb, 1536, 512, KAX);
    conv_w<<<(1536 * KA1 + 255) / 256, 256>>>(Whh, Whhb, 1536, 512, KA1);
    conv_w<<<(128 * KA1 + 255) / 256, 256>>>(Wout, Woutb, 128, 512, KA1);
    conv_x<<<(BATCH * T_STEPS * KAX + 255) / 256, 256>>>(x, xb);

    // ALL timesteps' input-side GRU GEMM, batched: gi[s*512+r] = x_s @ Wih^T + bih
    {
        GemmP pg1 = {};
        pg1.A = xb; pg1.Ka = KAX; pg1.W = Wihb; pg1.K = KEX; pg1.bias = bih;
        pg1.Cf = gi; pg1.ldc = 1536;
        gemm_mma<0><<<dim3(24, 64), 256, SMEM_BYTES>>>(pg1);   // M=4096, N=1536
    }

    // the whole sequential chain in ONE persistent kernel
    seq_kernel<<<GRID_P, 256, SMEM_BYTES>>>(
        ts, b1, b2, b3, bhh, bout,
        W1b, W2b, W3b, Whhb, Woutb,
        A1, z1b, z2b, gi, gh, h, acc, out);
}